// round 10
// baseline (speedup 1.0000x reference)
#include <cuda_runtime.h>
#include <cuda_fp16.h>
#include <math.h>

// FlowMatching: per-batch Gaussian blur (separable, K=9, sigma=0.1+0.9*t[b],
// dynamic radius mask r=ceil(4*sigma), zero padding) + lerp t*blur + (1-t)*x.
// x1: [128, 3, 512, 512] fp32, t: [128] fp32, out: same as x1.
//
// R9: extend packed fp32x2 FMA to phase H (36 FFMA -> 18 FFMA2 per quad;
// even pairs free from LDG.128 quads) and to the lerp. Register guard:
// scalar weights dropped after packing, only 12/15 loads hoisted, to stay
// under the 85-reg cap of launch_bounds(256,3) without spills.

#define H 512
#define W 512
#define TW 128
#define TH 32
#define RAD 4
#define KS 9
#define HROWS (TH + 2 * RAD)   // 40

typedef unsigned long long u64;

__device__ __forceinline__ u64 packf2(float lo, float hi) {
    u64 r;
    asm("mov.b64 %0, {%1, %2};" : "=l"(r) : "f"(lo), "f"(hi));
    return r;
}
__device__ __forceinline__ u64 ffma2(u64 a, u64 b, u64 c) {
    u64 d;
    asm("fma.rn.f32x2 %0, %1, %2, %3;" : "=l"(d) : "l"(a), "l"(b), "l"(c));
    return d;
}
__device__ __forceinline__ u64 mulf2(u64 a, u64 b) {
    u64 d;
    asm("mul.rn.f32x2 %0, %1, %2;" : "=l"(d) : "l"(a), "l"(b));
    return d;
}
__device__ __forceinline__ void unpackf2(u64 v, float& lo, float& hi) {
    asm("mov.b64 {%0, %1}, %2;" : "=f"(lo), "=f"(hi) : "l"(v));
}

// horizontal 9-tap on 12 inputs (3 float4) -> one filtered quad, packed math
__device__ __forceinline__ void hfilter_quad(const float4& A, const float4& Bv,
                                             const float4& Cv, const u64* wp,
                                             u64& oxy, u64& ozw)
{
    // pairs p_j = (f_j, f_{j+1}); even j free from aligned quads
    u64 p0  = packf2(A.x,  A.y);
    u64 p1  = packf2(A.y,  A.z);
    u64 p2  = packf2(A.z,  A.w);
    u64 p3  = packf2(A.w,  Bv.x);
    u64 p4  = packf2(Bv.x, Bv.y);
    u64 p5  = packf2(Bv.y, Bv.z);
    u64 p6  = packf2(Bv.z, Bv.w);
    u64 p7  = packf2(Bv.w, Cv.x);
    u64 p8  = packf2(Cv.x, Cv.y);
    u64 p9  = packf2(Cv.y, Cv.z);
    u64 p10 = packf2(Cv.z, Cv.w);

    u64 a = mulf2(wp[0], p0);
    a = ffma2(wp[1], p1, a);
    a = ffma2(wp[2], p2, a);
    a = ffma2(wp[3], p3, a);
    a = ffma2(wp[4], p4, a);
    a = ffma2(wp[5], p5, a);
    a = ffma2(wp[6], p6, a);
    a = ffma2(wp[7], p7, a);
    a = ffma2(wp[8], p8, a);
    oxy = a;

    u64 b = mulf2(wp[0], p2);
    b = ffma2(wp[1], p3, b);
    b = ffma2(wp[2], p4, b);
    b = ffma2(wp[3], p5, b);
    b = ffma2(wp[4], p6, b);
    b = ffma2(wp[5], p7, b);
    b = ffma2(wp[6], p8, b);
    b = ffma2(wp[7], p9, b);
    b = ffma2(wp[8], p10, b);
    ozw = b;
}

__global__ __launch_bounds__(256, 3)
void flowmatch_blur_kernel(const float* __restrict__ x1,
                           const float* __restrict__ t,
                           float* __restrict__ out)
{
    __shared__ __align__(16) __half s_h[HROWS][TW];   // 10240 B

    const int tid   = threadIdx.x;
    const int plane = blockIdx.z;      // b*3 + c, 384 planes
    const int b     = plane / 3;
    const int x0    = blockIdx.x * TW;
    const int y0    = blockIdx.y * TH;

    const float tv = __ldg(&t[b]);

    // ---- normalized 1D gaussian weights -> packed pairs only ----
    u64 wp[KS];
    {
        float sigma  = __fadd_rn(0.1f, __fmul_rn(tv, 0.9f));
        float r      = ceilf(__fmul_rn(4.0f, sigma));
        float inv2s2 = 1.0f / (2.0f * sigma * sigma);
        float wl[KS];
        float sum = 0.0f;
        #pragma unroll
        for (int i = 0; i < KS; i++) {
            float c = (float)(i - RAD);
            float v = (fabsf(c) <= r) ? expf(-c * c * inv2s2) : 0.0f;
            wl[i] = v;
            sum += v;
        }
        float inv = 1.0f / sum;
        #pragma unroll
        for (int i = 0; i < KS; i++) {
            float w = wl[i] * inv;
            wp[i] = packf2(w, w);
        }
    }

    const float* pin  = x1  + (size_t)plane * (H * W);
    float*       pout = out + (size_t)plane * (H * W);

    const int q  = tid & 31;           // constant x-quad for this thread
    const int r0 = tid >> 5;           // base row
    const int gx = x0 + q * 4;

    // ---- Phase H: hoist 12 loads (4 iters), compute, then tail iter ----
    float4 Av[4], Bv[4], Cv[4];
    #pragma unroll
    for (int it = 0; it < 4; it++) {
        int row = r0 + it * 8;
        int gy  = y0 - RAD + row;
        Av[it] = make_float4(0.f, 0.f, 0.f, 0.f);
        Bv[it] = make_float4(0.f, 0.f, 0.f, 0.f);
        Cv[it] = make_float4(0.f, 0.f, 0.f, 0.f);
        if (gy >= 0 && gy < H) {
            const float* rp = pin + gy * W + gx;
            if (gx > 0)
                Av[it] = *reinterpret_cast<const float4*>(rp - 4);
            Bv[it] = *reinterpret_cast<const float4*>(rp);
            if (gx + 4 < W)
                Cv[it] = *reinterpret_cast<const float4*>(rp + 4);
        }
    }

    #pragma unroll
    for (int it = 0; it < 4; it++) {
        int row = r0 + it * 8;
        u64 oxy, ozw;
        hfilter_quad(Av[it], Bv[it], Cv[it], wp, oxy, ozw);
        float ox, oy, oz, ow;
        unpackf2(oxy, ox, oy);
        unpackf2(ozw, oz, ow);
        __half2 h01 = __floats2half2_rn(ox, oy);
        __half2 h23 = __floats2half2_rn(oz, ow);
        uint2 packed;
        packed.x = *reinterpret_cast<unsigned*>(&h01);
        packed.y = *reinterpret_cast<unsigned*>(&h23);
        *reinterpret_cast<uint2*>(&s_h[row][q * 4]) = packed;
    }

    // tail iteration (it = 4)
    {
        int row = r0 + 32;
        int gy  = y0 - RAD + row;
        float4 A  = make_float4(0.f, 0.f, 0.f, 0.f);
        float4 Bq = make_float4(0.f, 0.f, 0.f, 0.f);
        float4 Cq = make_float4(0.f, 0.f, 0.f, 0.f);
        if (gy >= 0 && gy < H) {
            const float* rp = pin + gy * W + gx;
            if (gx > 0)
                A = *reinterpret_cast<const float4*>(rp - 4);
            Bq = *reinterpret_cast<const float4*>(rp);
            if (gx + 4 < W)
                Cq = *reinterpret_cast<const float4*>(rp + 4);
        }
        u64 oxy, ozw;
        hfilter_quad(A, Bq, Cq, wp, oxy, ozw);
        float ox, oy, oz, ow;
        unpackf2(oxy, ox, oy);
        unpackf2(ozw, oz, ow);
        __half2 h01 = __floats2half2_rn(ox, oy);
        __half2 h23 = __floats2half2_rn(oz, ow);
        uint2 packed;
        packed.x = *reinterpret_cast<unsigned*>(&h01);
        packed.y = *reinterpret_cast<unsigned*>(&h23);
        *reinterpret_cast<uint2*>(&s_h[row][q * 4]) = packed;
    }

    __syncthreads();

    // ---- Phase V: vertical 9-tap with FFMA2, rolling 12-row window,
    //      4 stacked quads; packed lerp with orig from global ----
    {
        const int xq    = q * 4;
        const int ybase = r0 * 4;          // 0,4,...,28
        const float omt = 1.0f - tv;
        const u64 tvp   = packf2(tv, tv);
        const u64 omtp  = packf2(omt, omt);

        u64 a0lo=0, a0hi=0, a1lo=0, a1hi=0,
            a2lo=0, a2hi=0, a3lo=0, a3hi=0;

        #pragma unroll
        for (int r = 0; r < 12; r++) {
            uint2 raw = *reinterpret_cast<const uint2*>(&s_h[ybase + r][xq]);
            __half2 h01 = *reinterpret_cast<__half2*>(&raw.x);
            __half2 h23 = *reinterpret_cast<__half2*>(&raw.y);
            float2 lo = __half22float2(h01);
            float2 hi = __half22float2(h23);
            u64 plo = packf2(lo.x, lo.y);
            u64 phi = packf2(hi.x, hi.y);

            if (r <= 8) {
                a0lo = ffma2(wp[r], plo, a0lo);
                a0hi = ffma2(wp[r], phi, a0hi);
            }
            if (r >= 1 && r <= 9) {
                a1lo = ffma2(wp[r-1], plo, a1lo);
                a1hi = ffma2(wp[r-1], phi, a1hi);
            }
            if (r >= 2 && r <= 10) {
                a2lo = ffma2(wp[r-2], plo, a2lo);
                a2hi = ffma2(wp[r-2], phi, a2hi);
            }
            if (r >= 3) {
                a3lo = ffma2(wp[r-3], plo, a3lo);
                a3hi = ffma2(wp[r-3], phi, a3hi);
            }
        }

        u64 alo[4] = {a0lo, a1lo, a2lo, a3lo};
        u64 ahi[4] = {a0hi, a1hi, a2hi, a3hi};

        #pragma unroll
        for (int j = 0; j < 4; j++) {
            int gy = y0 + ybase + j;
            float4 orig = *reinterpret_cast<const float4*>(pin + gy * W + x0 + xq);

            u64 oxy = ffma2(tvp, alo[j], mulf2(omtp, packf2(orig.x, orig.y)));
            u64 ozw = ffma2(tvp, ahi[j], mulf2(omtp, packf2(orig.z, orig.w)));

            float4 o;
            unpackf2(oxy, o.x, o.y);
            unpackf2(ozw, o.z, o.w);
            *reinterpret_cast<float4*>(pout + gy * W + x0 + xq) = o;
        }
    }
}

extern "C" void kernel_launch(void* const* d_in, const int* in_sizes, int n_in,
                              void* d_out, int out_size)
{
    const float* x1 = (const float*)d_in[0];
    const float* t  = (const float*)d_in[1];
    float* out      = (float*)d_out;

    dim3 grid(W / TW, H / TH, 384);   // 4 x 16 x 384 = 24576 blocks
    dim3 block(256);
    flowmatch_blur_kernel<<<grid, block>>>(x1, t, out);
}

// round 11
// speedup vs baseline: 1.0500x; 1.0500x over previous
#include <cuda_runtime.h>
#include <cuda_fp16.h>
#include <math.h>

// FlowMatching: per-batch Gaussian blur (separable, K=9, sigma=0.1+0.9*t[b],
// dynamic radius mask r=ceil(4*sigma), zero padding) + lerp t*blur + (1-t)*x.
// x1: [128, 3, 512, 512] fp32, t: [128] fp32, out: same as x1.
//
// R10: R8 (best, 174us) with register diet for occupancy. R8 was issue-bound
// at occ 34% (80 regs, 3 blocks/SM). Phase-H loads now hoisted in two waves
// (9 + 6 float4) instead of 15, cutting peak regs to <=64 so
// launch_bounds(256,4) gives 32 warps/SM. Scalar phase-H math (4 indep FMA
// chains — R9 proved packed H loses ILP), packed FFMA2 phase-V (R8 win).

#define H 512
#define W 512
#define TW 128
#define TH 32
#define RAD 4
#define KS 9
#define HROWS (TH + 2 * RAD)   // 40

typedef unsigned long long u64;

__device__ __forceinline__ u64 packf2(float lo, float hi) {
    u64 r;
    asm("mov.b64 %0, {%1, %2};" : "=l"(r) : "f"(lo), "f"(hi));
    return r;
}
__device__ __forceinline__ u64 ffma2(u64 a, u64 b, u64 c) {
    u64 d;
    asm("fma.rn.f32x2 %0, %1, %2, %3;" : "=l"(d) : "l"(a), "l"(b), "l"(c));
    return d;
}
__device__ __forceinline__ u64 mulf2(u64 a, u64 b) {
    u64 d;
    asm("mul.rn.f32x2 %0, %1, %2;" : "=l"(d) : "l"(a), "l"(b));
    return d;
}
__device__ __forceinline__ void unpackf2(u64 v, float& lo, float& hi) {
    asm("mov.b64 {%0, %1}, %2;" : "=f"(lo), "=f"(hi) : "l"(v));
}

__global__ __launch_bounds__(256, 4)
void flowmatch_blur_kernel(const float* __restrict__ x1,
                           const float* __restrict__ t,
                           float* __restrict__ out)
{
    __shared__ __align__(16) __half s_h[HROWS][TW];   // 10240 B

    const int tid   = threadIdx.x;
    const int plane = blockIdx.z;      // b*3 + c, 384 planes
    const int b     = plane / 3;
    const int x0    = blockIdx.x * TW;
    const int y0    = blockIdx.y * TH;

    const float tv = __ldg(&t[b]);

    // ---- normalized 1D gaussian weights (scalar, used by phase H) ----
    float w0,w1,w2,w3,w4,w5,w6,w7,w8;
    {
        float sigma  = __fadd_rn(0.1f, __fmul_rn(tv, 0.9f));
        float r      = ceilf(__fmul_rn(4.0f, sigma));
        float inv2s2 = 1.0f / (2.0f * sigma * sigma);
        float wl[KS];
        float sum = 0.0f;
        #pragma unroll
        for (int i = 0; i < KS; i++) {
            float c = (float)(i - RAD);
            float v = (fabsf(c) <= r) ? expf(-c * c * inv2s2) : 0.0f;
            wl[i] = v;
            sum += v;
        }
        float inv = 1.0f / sum;
        w0=wl[0]*inv; w1=wl[1]*inv; w2=wl[2]*inv; w3=wl[3]*inv; w4=wl[4]*inv;
        w5=wl[5]*inv; w6=wl[6]*inv; w7=wl[7]*inv; w8=wl[8]*inv;
    }

    const float* pin  = x1  + (size_t)plane * (H * W);
    float*       pout = out + (size_t)plane * (H * W);

    const int q  = tid & 31;
    const int r0 = tid >> 5;
    const int gx = x0 + q * 4;

    // ---- Phase H: two load waves (9 + 6 float4) to cap regs at ~64 ----
    // scalar filter: 4 independent FMA chains per quad (max ILP).
    #pragma unroll
    for (int wave = 0; wave < 2; wave++) {
        const int nit = (wave == 0) ? 3 : 2;
        float4 Av[3], Bv[3], Cv[3];

        #pragma unroll
        for (int i = 0; i < 3; i++) {
            if (i >= nit) break;
            int it  = (wave == 0) ? i : (3 + i);
            int row = r0 + it * 8;
            int gy  = y0 - RAD + row;
            Av[i] = make_float4(0.f, 0.f, 0.f, 0.f);
            Bv[i] = make_float4(0.f, 0.f, 0.f, 0.f);
            Cv[i] = make_float4(0.f, 0.f, 0.f, 0.f);
            if (gy >= 0 && gy < H) {
                const float* rp = pin + gy * W + gx;
                if (gx > 0)
                    Av[i] = *reinterpret_cast<const float4*>(rp - 4);
                Bv[i] = *reinterpret_cast<const float4*>(rp);
                if (gx + 4 < W)
                    Cv[i] = *reinterpret_cast<const float4*>(rp + 4);
            }
        }

        #pragma unroll
        for (int i = 0; i < 3; i++) {
            if (i >= nit) break;
            int it  = (wave == 0) ? i : (3 + i);
            int row = r0 + it * 8;

            float f0=Av[i].x, f1=Av[i].y, f2=Av[i].z,  f3=Av[i].w;
            float f4=Bv[i].x, f5=Bv[i].y, f6=Bv[i].z,  f7=Bv[i].w;
            float f8=Cv[i].x, f9=Cv[i].y, f10=Cv[i].z, f11=Cv[i].w;

            float4 o;
            o.x = w0*f0 + w1*f1 + w2*f2 + w3*f3 + w4*f4 + w5*f5 + w6*f6 + w7*f7 + w8*f8;
            o.y = w0*f1 + w1*f2 + w2*f3 + w3*f4 + w4*f5 + w5*f6 + w6*f7 + w7*f8 + w8*f9;
            o.z = w0*f2 + w1*f3 + w2*f4 + w3*f5 + w4*f6 + w5*f7 + w6*f8 + w7*f9 + w8*f10;
            o.w = w0*f3 + w1*f4 + w2*f5 + w3*f6 + w4*f7 + w5*f8 + w6*f9 + w7*f10 + w8*f11;

            __half2 h01 = __floats2half2_rn(o.x, o.y);
            __half2 h23 = __floats2half2_rn(o.z, o.w);
            uint2 packed;
            packed.x = *reinterpret_cast<unsigned*>(&h01);
            packed.y = *reinterpret_cast<unsigned*>(&h23);
            *reinterpret_cast<uint2*>(&s_h[row][q * 4]) = packed;
        }
    }

    __syncthreads();

    // ---- Phase V: vertical 9-tap with FFMA2, rolling 12-row window,
    //      4 stacked quads; packed lerp with orig reloaded from global ----
    {
        const int xq    = q * 4;
        const int ybase = r0 * 4;          // 0,4,...,28
        const float omt = 1.0f - tv;

        // packed weight pairs, built AFTER phase H (no reg-lifetime overlap)
        u64 wp[KS];
        wp[0]=packf2(w0,w0); wp[1]=packf2(w1,w1); wp[2]=packf2(w2,w2);
        wp[3]=packf2(w3,w3); wp[4]=packf2(w4,w4); wp[5]=packf2(w5,w5);
        wp[6]=packf2(w6,w6); wp[7]=packf2(w7,w7); wp[8]=packf2(w8,w8);

        u64 a0lo=0, a0hi=0, a1lo=0, a1hi=0,
            a2lo=0, a2hi=0, a3lo=0, a3hi=0;

        #pragma unroll
        for (int r = 0; r < 12; r++) {
            uint2 raw = *reinterpret_cast<const uint2*>(&s_h[ybase + r][xq]);
            __half2 h01 = *reinterpret_cast<__half2*>(&raw.x);
            __half2 h23 = *reinterpret_cast<__half2*>(&raw.y);
            float2 lo = __half22float2(h01);
            float2 hi = __half22float2(h23);
            u64 plo = packf2(lo.x, lo.y);
            u64 phi = packf2(hi.x, hi.y);

            if (r <= 8) {
                a0lo = ffma2(wp[r], plo, a0lo);
                a0hi = ffma2(wp[r], phi, a0hi);
            }
            if (r >= 1 && r <= 9) {
                a1lo = ffma2(wp[r-1], plo, a1lo);
                a1hi = ffma2(wp[r-1], phi, a1hi);
            }
            if (r >= 2 && r <= 10) {
                a2lo = ffma2(wp[r-2], plo, a2lo);
                a2hi = ffma2(wp[r-2], phi, a2hi);
            }
            if (r >= 3) {                      // r max 11 -> weight idx max 8
                a3lo = ffma2(wp[r-3], plo, a3lo);
                a3hi = ffma2(wp[r-3], phi, a3hi);
            }
        }

        u64 alo[4] = {a0lo, a1lo, a2lo, a3lo};
        u64 ahi[4] = {a0hi, a1hi, a2hi, a3hi};

        const u64 tvp  = packf2(tv, tv);
        const u64 omtp = packf2(omt, omt);

        #pragma unroll
        for (int j = 0; j < 4; j++) {
            int gy = y0 + ybase + j;
            float4 orig = *reinterpret_cast<const float4*>(pin + gy * W + x0 + xq);

            u64 oxy = ffma2(tvp, alo[j], mulf2(omtp, packf2(orig.x, orig.y)));
            u64 ozw = ffma2(tvp, ahi[j], mulf2(omtp, packf2(orig.z, orig.w)));

            float4 o;
            unpackf2(oxy, o.x, o.y);
            unpackf2(ozw, o.z, o.w);
            *reinterpret_cast<float4*>(pout + gy * W + x0 + xq) = o;
        }
    }
}

extern "C" void kernel_launch(void* const* d_in, const int* in_sizes, int n_in,
                              void* d_out, int out_size)
{
    const float* x1 = (const float*)d_in[0];
    const float* t  = (const float*)d_in[1];
    float* out      = (float*)d_out;

    dim3 grid(W / TW, H / TH, 384);   // 4 x 16 x 384 = 24576 blocks
    dim3 block(256);
    flowmatch_blur_kernel<<<grid, block>>>(x1, t, out);
}

// round 12
// speedup vs baseline: 1.0836x; 1.0321x over previous
#include <cuda_runtime.h>
#include <math.h>

// FlowMatching: per-batch Gaussian blur (separable, K=9, sigma=0.1+0.9*t[b],
// dynamic radius mask r=ceil(4*sigma), zero padding) + lerp t*blur + (1-t)*x.
// x1: [128, 3, 512, 512] fp32, t: [128] fp32, out: same as x1.
//
// R11: R8 structure (best: 15 hoisted LDG, scalar phase-H, FFMA2 phase-V,
// launch_bounds(256,3)) but s_h back to fp32 and ALL packed operands taken
// bitwise from 128-bit loads (smem ulonglong2, global ulonglong2): zero
// F2F cvts, zero MOV packs in phase V / lerp. ~-20% issue slots vs R8 and
// full fp32 precision restored.

#define H 512
#define W 512
#define TW 128
#define TH 32
#define RAD 4
#define KS 9
#define HROWS (TH + 2 * RAD)   // 40

typedef unsigned long long u64;

__device__ __forceinline__ u64 packf2(float lo, float hi) {
    u64 r;
    asm("mov.b64 %0, {%1, %2};" : "=l"(r) : "f"(lo), "f"(hi));
    return r;
}
__device__ __forceinline__ u64 ffma2(u64 a, u64 b, u64 c) {
    u64 d;
    asm("fma.rn.f32x2 %0, %1, %2, %3;" : "=l"(d) : "l"(a), "l"(b), "l"(c));
    return d;
}
__device__ __forceinline__ u64 mulf2(u64 a, u64 b) {
    u64 d;
    asm("mul.rn.f32x2 %0, %1, %2;" : "=l"(d) : "l"(a), "l"(b));
    return d;
}

__global__ __launch_bounds__(256, 3)
void flowmatch_blur_kernel(const float* __restrict__ x1,
                           const float* __restrict__ t,
                           float* __restrict__ out)
{
    __shared__ __align__(16) float s_h[HROWS][TW];   // 20480 B

    const int tid   = threadIdx.x;
    const int plane = blockIdx.z;      // b*3 + c, 384 planes
    const int b     = plane / 3;
    const int x0    = blockIdx.x * TW;
    const int y0    = blockIdx.y * TH;

    const float tv = __ldg(&t[b]);

    // ---- normalized 1D gaussian weights (scalar, phase H) ----
    float w0,w1,w2,w3,w4,w5,w6,w7,w8;
    {
        float sigma  = __fadd_rn(0.1f, __fmul_rn(tv, 0.9f));
        float r      = ceilf(__fmul_rn(4.0f, sigma));
        float inv2s2 = 1.0f / (2.0f * sigma * sigma);
        float wl[KS];
        float sum = 0.0f;
        #pragma unroll
        for (int i = 0; i < KS; i++) {
            float c = (float)(i - RAD);
            float v = (fabsf(c) <= r) ? expf(-c * c * inv2s2) : 0.0f;
            wl[i] = v;
            sum += v;
        }
        float inv = 1.0f / sum;
        w0=wl[0]*inv; w1=wl[1]*inv; w2=wl[2]*inv; w3=wl[3]*inv; w4=wl[4]*inv;
        w5=wl[5]*inv; w6=wl[6]*inv; w7=wl[7]*inv; w8=wl[8]*inv;
    }

    const float* pin  = x1  + (size_t)plane * (H * W);
    float*       pout = out + (size_t)plane * (H * W);

    const int q  = tid & 31;
    const int r0 = tid >> 5;
    const int gx = x0 + q * 4;

    // ---- Phase H: hoist all 15 float4 loads (max MLP), scalar filter ----
    float4 Av[5], Bv[5], Cv[5];
    #pragma unroll
    for (int it = 0; it < 5; it++) {
        int row = r0 + it * 8;
        int gy  = y0 - RAD + row;
        Av[it] = make_float4(0.f, 0.f, 0.f, 0.f);
        Bv[it] = make_float4(0.f, 0.f, 0.f, 0.f);
        Cv[it] = make_float4(0.f, 0.f, 0.f, 0.f);
        if (gy >= 0 && gy < H) {
            const float* rp = pin + gy * W + gx;
            if (gx > 0)
                Av[it] = *reinterpret_cast<const float4*>(rp - 4);
            Bv[it] = *reinterpret_cast<const float4*>(rp);
            if (gx + 4 < W)
                Cv[it] = *reinterpret_cast<const float4*>(rp + 4);
        }
    }

    #pragma unroll
    for (int it = 0; it < 5; it++) {
        int row = r0 + it * 8;

        float f0=Av[it].x, f1=Av[it].y, f2=Av[it].z,  f3=Av[it].w;
        float f4=Bv[it].x, f5=Bv[it].y, f6=Bv[it].z,  f7=Bv[it].w;
        float f8=Cv[it].x, f9=Cv[it].y, f10=Cv[it].z, f11=Cv[it].w;

        float4 o;
        o.x = w0*f0 + w1*f1 + w2*f2 + w3*f3 + w4*f4 + w5*f5 + w6*f6 + w7*f7 + w8*f8;
        o.y = w0*f1 + w1*f2 + w2*f3 + w3*f4 + w4*f5 + w5*f6 + w6*f7 + w7*f8 + w8*f9;
        o.z = w0*f2 + w1*f3 + w2*f4 + w3*f5 + w4*f6 + w5*f7 + w6*f8 + w7*f9 + w8*f10;
        o.w = w0*f3 + w1*f4 + w2*f5 + w3*f6 + w4*f7 + w5*f8 + w6*f9 + w7*f10 + w8*f11;

        // raw fp32 store, single STS.128
        *reinterpret_cast<float4*>(&s_h[row][q * 4]) = o;
    }

    __syncthreads();

    // ---- Phase V: vertical 9-tap, FFMA2 on bitwise (f32,f32) pairs from
    //      LDS.128; rolling 12-row window, 4 stacked quads; packed lerp ----
    {
        const int xq    = q * 4;
        const int ybase = r0 * 4;          // 0,4,...,28
        const float omt = 1.0f - tv;

        u64 wp[KS];
        wp[0]=packf2(w0,w0); wp[1]=packf2(w1,w1); wp[2]=packf2(w2,w2);
        wp[3]=packf2(w3,w3); wp[4]=packf2(w4,w4); wp[5]=packf2(w5,w5);
        wp[6]=packf2(w6,w6); wp[7]=packf2(w7,w7); wp[8]=packf2(w8,w8);

        u64 a0lo=0, a0hi=0, a1lo=0, a1hi=0,
            a2lo=0, a2hi=0, a3lo=0, a3hi=0;

        #pragma unroll
        for (int r = 0; r < 12; r++) {
            // one LDS.128 -> two packed f32x2 operands, no cvt/pack
            ulonglong2 hv = *reinterpret_cast<const ulonglong2*>(&s_h[ybase + r][xq]);
            u64 plo = hv.x;
            u64 phi = hv.y;

            if (r <= 8) {
                a0lo = ffma2(wp[r], plo, a0lo);
                a0hi = ffma2(wp[r], phi, a0hi);
            }
            if (r >= 1 && r <= 9) {
                a1lo = ffma2(wp[r-1], plo, a1lo);
                a1hi = ffma2(wp[r-1], phi, a1hi);
            }
            if (r >= 2 && r <= 10) {
                a2lo = ffma2(wp[r-2], plo, a2lo);
                a2hi = ffma2(wp[r-2], phi, a2hi);
            }
            if (r >= 3) {                      // r max 11 -> weight idx max 8
                a3lo = ffma2(wp[r-3], plo, a3lo);
                a3hi = ffma2(wp[r-3], phi, a3hi);
            }
        }

        u64 alo[4] = {a0lo, a1lo, a2lo, a3lo};
        u64 ahi[4] = {a0hi, a1hi, a2hi, a3hi};

        const u64 tvp  = packf2(tv, tv);
        const u64 omtp = packf2(omt, omt);

        #pragma unroll
        for (int j = 0; j < 4; j++) {
            int gy = y0 + ybase + j;
            // orig as bitwise pairs straight from LDG.128
            ulonglong2 og = *reinterpret_cast<const ulonglong2*>(pin + gy * W + x0 + xq);

            ulonglong2 res;
            res.x = ffma2(tvp, alo[j], mulf2(omtp, og.x));
            res.y = ffma2(tvp, ahi[j], mulf2(omtp, og.y));

            *reinterpret_cast<ulonglong2*>(pout + gy * W + x0 + xq) = res;
        }
    }
}

extern "C" void kernel_launch(void* const* d_in, const int* in_sizes, int n_in,
                              void* d_out, int out_size)
{
    const float* x1 = (const float*)d_in[0];
    const float* t  = (const float*)d_in[1];
    float* out      = (float*)d_out;

    dim3 grid(W / TW, H / TH, 384);   // 4 x 16 x 384 = 24576 blocks
    dim3 block(256);
    flowmatch_blur_kernel<<<grid, block>>>(x1, t, out);
}

// round 14
// speedup vs baseline: 1.2686x; 1.1706x over previous
#include <cuda_runtime.h>
#include <cuda_fp16.h>
#include <cstdint>
#include <math.h>

// FlowMatching: per-batch Gaussian blur (separable, K=9, sigma=0.1+0.9*t[b],
// dynamic radius mask r=ceil(4*sigma), zero padding) + lerp t*blur + (1-t)*x.
// x1: [128, 3, 512, 512] fp32, t: [128] fp32, out: same as x1.
//
// R13 = R12 with the missing <cstdint> include (compile fix only).
// R12 theory: attack the DRAM-idle-during-compute plateau (R8/R10/R11 all
// ~175us, DRAM stuck 54%, nothing saturated). Block = column strip of 8
// TH=32 tiles; raw tiles double-buffered in smem via cp.async (zfill
// padding, zero reg cost) so tile i+1's DRAM reads overlap tile i's
// compute. Phase H: 3 LDS.128/quad from raw smem. Phase V: fp16 s_h +
// FFMA2. Lerp orig from raw smem (no LDG). 53.8KB dynamic smem.

#define H 512
#define W 512
#define TW 128
#define TH 32
#define RAD 4
#define KS 9
#define P_TILES 8
#define RAW_W 136                     // 128 + 2*4 halo cols
#define RAW_H 40                      // 32 + 2*4 halo rows
#define RAW_BYTES (RAW_H * RAW_W * 4) // 21760
#define SH_BYTES  (RAW_H * TW * 2)    // 10240 (fp16 h-filtered)
#define SMEM_BYTES (2 * RAW_BYTES + SH_BYTES)  // 53760

typedef unsigned long long u64;
typedef unsigned int u32;

__device__ __forceinline__ u64 packf2(float lo, float hi) {
    u64 r;
    asm("mov.b64 %0, {%1, %2};" : "=l"(r) : "f"(lo), "f"(hi));
    return r;
}
__device__ __forceinline__ u64 ffma2(u64 a, u64 b, u64 c) {
    u64 d;
    asm("fma.rn.f32x2 %0, %1, %2, %3;" : "=l"(d) : "l"(a), "l"(b), "l"(c));
    return d;
}
__device__ __forceinline__ u64 mulf2(u64 a, u64 b) {
    u64 d;
    asm("mul.rn.f32x2 %0, %1, %2;" : "=l"(d) : "l"(a), "l"(b));
    return d;
}

// prefetch one 40x136 raw tile (float) into smem via cp.async, zero-filling
// out-of-image quads (src_size=0). 40*34 = 1360 16B ops across 256 threads.
__device__ __forceinline__ void prefetch_tile(const float* __restrict__ pin,
                                              int y0, int x0,
                                              float* rawbuf, int tid)
{
    u32 sbase = (u32)__cvta_generic_to_shared(rawbuf);
    #pragma unroll
    for (int k = 0; k < 6; k++) {
        int idx = tid + k * 256;
        if (idx < RAW_H * 34) {
            int row = idx / 34;
            int c   = idx - row * 34;          // 0..33 quad within row
            int gy  = y0 - RAD + row;
            int gxq = x0 - RAD + c * 4;        // 16B-aligned global x
            bool ok = (gy >= 0) && (gy < H) && (gxq >= 0) && (gxq < W);
            const float* src = ok ? (pin + gy * W + gxq) : pin;
            unsigned sz = ok ? 16u : 0u;
            u32 dst = sbase + (u32)(row * RAW_W + c * 4) * 4u;
            asm volatile("cp.async.cg.shared.global [%0], [%1], 16, %2;"
                         :: "r"(dst), "l"(src), "r"(sz));
        }
    }
}

__global__ __launch_bounds__(256, 3)
void flowmatch_blur_kernel(const float* __restrict__ x1,
                           const float* __restrict__ t,
                           float* __restrict__ out)
{
    extern __shared__ __align__(16) unsigned char smem[];
    float*  raw0 = (float*)(smem);
    float*  raw1 = (float*)(smem + RAW_BYTES);
    __half* s_h  = (__half*)(smem + 2 * RAW_BYTES);

    const int tid   = threadIdx.x;
    const int plane = blockIdx.z;              // b*3 + c, 384 planes
    const int b     = plane / 3;
    const int x0    = blockIdx.x * TW;
    const int ystrip = blockIdx.y * (P_TILES * TH);

    const float tv = __ldg(&t[b]);

    // ---- normalized 1D gaussian weights ----
    float w0,w1,w2,w3,w4,w5,w6,w7,w8;
    {
        float sigma  = __fadd_rn(0.1f, __fmul_rn(tv, 0.9f));
        float r      = ceilf(__fmul_rn(4.0f, sigma));
        float inv2s2 = 1.0f / (2.0f * sigma * sigma);
        float wl[KS];
        float sum = 0.0f;
        #pragma unroll
        for (int i = 0; i < KS; i++) {
            float c = (float)(i - RAD);
            float v = (fabsf(c) <= r) ? expf(-c * c * inv2s2) : 0.0f;
            wl[i] = v;
            sum += v;
        }
        float inv = 1.0f / sum;
        w0=wl[0]*inv; w1=wl[1]*inv; w2=wl[2]*inv; w3=wl[3]*inv; w4=wl[4]*inv;
        w5=wl[5]*inv; w6=wl[6]*inv; w7=wl[7]*inv; w8=wl[8]*inv;
    }

    u64 wp[KS];
    wp[0]=packf2(w0,w0); wp[1]=packf2(w1,w1); wp[2]=packf2(w2,w2);
    wp[3]=packf2(w3,w3); wp[4]=packf2(w4,w4); wp[5]=packf2(w5,w5);
    wp[6]=packf2(w6,w6); wp[7]=packf2(w7,w7); wp[8]=packf2(w8,w8);

    const float* pin  = x1  + (size_t)plane * (H * W);
    float*       pout = out + (size_t)plane * (H * W);

    const int q  = tid & 31;
    const int r0 = tid >> 5;

    // prologue: prefetch tile 0
    prefetch_tile(pin, ystrip, x0, raw0, tid);
    asm volatile("cp.async.commit_group;");

    for (int i = 0; i < P_TILES; i++) {
        const int y0 = ystrip + i * TH;
        float* cur = (i & 1) ? raw1 : raw0;
        float* nxt = (i & 1) ? raw0 : raw1;

        // wait for tile i's data, then make visible to all threads.
        // (top sync also guarantees everyone finished phase V of tile i-1,
        //  so prefetching into `nxt` — the buffer V(i-1) read — is safe.)
        asm volatile("cp.async.wait_group 0;");
        __syncthreads();

        if (i + 1 < P_TILES) {
            prefetch_tile(pin, y0 + TH, x0, nxt, tid);
            asm volatile("cp.async.commit_group;");
        }

        // ---- Phase H: 3 LDS.128 per quad from raw, scalar 9-tap, fp16 STS ----
        #pragma unroll
        for (int k = 0; k < 5; k++) {
            int idx = tid + k * 256;       // 0..1279
            int row = idx >> 5;            // 0..39
            int qx  = idx & 31;            // 0..31
            const float* rp = cur + row * RAW_W + qx * 4;
            float4 A  = *reinterpret_cast<const float4*>(rp);
            float4 Bv = *reinterpret_cast<const float4*>(rp + 4);
            float4 Cv = *reinterpret_cast<const float4*>(rp + 8);

            float f0=A.x,  f1=A.y,  f2=A.z,  f3=A.w;
            float f4=Bv.x, f5=Bv.y, f6=Bv.z, f7=Bv.w;
            float f8=Cv.x, f9=Cv.y, f10=Cv.z, f11=Cv.w;

            float4 o;
            o.x = w0*f0 + w1*f1 + w2*f2 + w3*f3 + w4*f4 + w5*f5 + w6*f6 + w7*f7 + w8*f8;
            o.y = w0*f1 + w1*f2 + w2*f3 + w3*f4 + w4*f5 + w5*f6 + w6*f7 + w7*f8 + w8*f9;
            o.z = w0*f2 + w1*f3 + w2*f4 + w3*f5 + w4*f6 + w5*f7 + w6*f8 + w7*f9 + w8*f10;
            o.w = w0*f3 + w1*f4 + w2*f5 + w3*f6 + w4*f7 + w5*f8 + w6*f9 + w7*f10 + w8*f11;

            __half2 h01 = __floats2half2_rn(o.x, o.y);
            __half2 h23 = __floats2half2_rn(o.z, o.w);
            uint2 packed;
            packed.x = *reinterpret_cast<unsigned*>(&h01);
            packed.y = *reinterpret_cast<unsigned*>(&h23);
            *reinterpret_cast<uint2*>(&s_h[row * TW + qx * 4]) = packed;
        }

        __syncthreads();

        // ---- Phase V: FFMA2 vertical 9-tap, rolling 12-row window,
        //      4 stacked quads; lerp orig from raw smem ----
        {
            const int xq    = q * 4;
            const int ybase = r0 * 4;      // 0,4,...,28
            const float omt = 1.0f - tv;

            u64 a0lo=0, a0hi=0, a1lo=0, a1hi=0,
                a2lo=0, a2hi=0, a3lo=0, a3hi=0;

            #pragma unroll
            for (int r = 0; r < 12; r++) {
                uint2 rawh = *reinterpret_cast<const uint2*>(&s_h[(ybase + r) * TW + xq]);
                __half2 h01 = *reinterpret_cast<__half2*>(&rawh.x);
                __half2 h23 = *reinterpret_cast<__half2*>(&rawh.y);
                float2 lo = __half22float2(h01);
                float2 hi = __half22float2(h23);
                u64 plo = packf2(lo.x, lo.y);
                u64 phi = packf2(hi.x, hi.y);

                if (r <= 8) {
                    a0lo = ffma2(wp[r], plo, a0lo);
                    a0hi = ffma2(wp[r], phi, a0hi);
                }
                if (r >= 1 && r <= 9) {
                    a1lo = ffma2(wp[r-1], plo, a1lo);
                    a1hi = ffma2(wp[r-1], phi, a1hi);
                }
                if (r >= 2 && r <= 10) {
                    a2lo = ffma2(wp[r-2], plo, a2lo);
                    a2hi = ffma2(wp[r-2], phi, a2hi);
                }
                if (r >= 3) {                  // r max 11 -> weight idx max 8
                    a3lo = ffma2(wp[r-3], plo, a3lo);
                    a3hi = ffma2(wp[r-3], phi, a3hi);
                }
            }

            u64 alo[4] = {a0lo, a1lo, a2lo, a3lo};
            u64 ahi[4] = {a0hi, a1hi, a2hi, a3hi};

            const u64 tvp  = packf2(tv, tv);
            const u64 omtp = packf2(omt, omt);

            #pragma unroll
            for (int j = 0; j < 4; j++) {
                int ly = ybase + j;
                // orig = raw[ly+4][xq+4 ..] (interior of raw tile), 16B aligned
                ulonglong2 og = *reinterpret_cast<const ulonglong2*>(
                    cur + (ly + RAD) * RAW_W + xq + RAD);

                ulonglong2 res;
                res.x = ffma2(tvp, alo[j], mulf2(omtp, og.x));
                res.y = ffma2(tvp, ahi[j], mulf2(omtp, og.y));

                *reinterpret_cast<ulonglong2*>(pout + (size_t)(y0 + ly) * W + x0 + xq) = res;
            }
        }
    }
}

extern "C" void kernel_launch(void* const* d_in, const int* in_sizes, int n_in,
                              void* d_out, int out_size)
{
    const float* x1 = (const float*)d_in[0];
    const float* t  = (const float*)d_in[1];
    float* out      = (float*)d_out;

    cudaFuncSetAttribute(flowmatch_blur_kernel,
                         cudaFuncAttributeMaxDynamicSharedMemorySize, SMEM_BYTES);

    // 4 x-tiles, 2 y-strips (8 tiles each), 384 planes = 3072 blocks
    dim3 grid(W / TW, H / (P_TILES * TH), 384);
    dim3 block(256);
    flowmatch_blur_kernel<<<grid, block, SMEM_BYTES>>>(x1, t, out);
}